// round 2
// baseline (speedup 1.0000x reference)
#include <cuda_runtime.h>

#define NN 30000
#define DD 32
#define HH 128
#define KK 10

// Scratch (allocation-free rule: __device__ globals)
__device__ float g_buf[NN * HH];   // g = feature @ W2, 15.36 MB (L2-resident)
__device__ float g_va[HH];
__device__ float g_vc[HH];
__device__ float g_bias[HH];

// ---------------------------------------------------------------------------
// Precompute: va[j] = sum_h max(Wt4[h],0)*Wt3[h,j], vc = min-part, bias sum.
// ---------------------------------------------------------------------------
__global__ void pre_kernel(const float* __restrict__ Wt3,
                           const float* __restrict__ Wt4,
                           const float* __restrict__ b0,
                           const float* __restrict__ b1,
                           const float* __restrict__ b2) {
    int j = threadIdx.x;
    float va = 0.f, vc = 0.f;
#pragma unroll 8
    for (int h = 0; h < HH; h++) {
        float t  = Wt4[h];
        float w3 = Wt3[h * HH + j];
        va += fmaxf(t, 0.f) * w3;
        vc += fminf(t, 0.f) * w3;
    }
    g_va[j]   = va;
    g_vc[j]   = vc;
    g_bias[j] = b0[j] + b1[j] + b2[j];
}

// ---------------------------------------------------------------------------
// g = feature @ W2   ([NN,128] x [128,128] fp32)
// BM=128, BN=128, BK=32 (4 K-chunks). 256 threads, 8x8 micro-tile per thread.
// Static smem: As 16KB + Bs 16KB = 32KB (< 48KB cap).
// ---------------------------------------------------------------------------
__global__ __launch_bounds__(256) void gemm_kernel(const float* __restrict__ A,
                                                   const float* __restrict__ B) {
    __shared__ float As[128][32];   // [m][k-in-chunk]
    __shared__ float Bs[32][128];   // [k-in-chunk][n]
    const int tid  = threadIdx.x;
    const int row0 = blockIdx.x * 128;

    const int tx = tid & 15;   // output-column group (8 cols each)
    const int ty = tid >> 4;   // output-row group (8 rows each)

    float acc[8][8];
#pragma unroll
    for (int i = 0; i < 8; i++)
#pragma unroll
        for (int j = 0; j < 8; j++) acc[i][j] = 0.f;

    for (int kk = 0; kk < 4; kk++) {
        // Load A tile: 128 rows x 32 cols = 1024 float4, 4 per thread.
#pragma unroll
        for (int i = 0; i < 4; i++) {
            int f = tid + i * 256;
            int m = f >> 3;          // row within tile
            int q = f & 7;           // float4 index within 32-col chunk
            int row = row0 + m;
            float4 v = make_float4(0.f, 0.f, 0.f, 0.f);
            if (row < NN)
                v = reinterpret_cast<const float4*>(A)[row * 32 + kk * 8 + q];
            *reinterpret_cast<float4*>(&As[m][q * 4]) = v;
        }
        // Load B tile: 32 rows x 128 cols = 1024 float4, 4 per thread.
#pragma unroll
        for (int i = 0; i < 4; i++) {
            int f = tid + i * 256;
            int r = f >> 5;          // k-row within chunk
            int q = f & 31;          // float4 index within 128-col row
            float4 v = reinterpret_cast<const float4*>(B)[(kk * 32 + r) * 32 + q];
            *reinterpret_cast<float4*>(&Bs[r][q * 4]) = v;
        }
        __syncthreads();

#pragma unroll
        for (int k = 0; k < 32; k++) {
            float a[8], b[8];
#pragma unroll
            for (int i = 0; i < 8; i++) a[i] = As[ty * 8 + i][k];
            float4 bl = *reinterpret_cast<float4*>(&Bs[k][tx * 8]);
            float4 bh = *reinterpret_cast<float4*>(&Bs[k][tx * 8 + 4]);
            b[0] = bl.x; b[1] = bl.y; b[2] = bl.z; b[3] = bl.w;
            b[4] = bh.x; b[5] = bh.y; b[6] = bh.z; b[7] = bh.w;
#pragma unroll
            for (int i = 0; i < 8; i++)
#pragma unroll
                for (int j = 0; j < 8; j++) acc[i][j] = fmaf(a[i], b[j], acc[i][j]);
        }
        __syncthreads();
    }

#pragma unroll
    for (int i = 0; i < 8; i++) {
        int row = row0 + ty * 8 + i;
        if (row < NN) {
            float4* out = reinterpret_cast<float4*>(&g_buf[row * HH + tx * 8]);
            out[0] = make_float4(acc[i][0], acc[i][1], acc[i][2], acc[i][3]);
            out[1] = make_float4(acc[i][4], acc[i][5], acc[i][6], acc[i][7]);
        }
    }
}

// ---------------------------------------------------------------------------
// Fused gather + epilogue. One block (128 threads) per node.
// out[n,j] = relu( bias[j] + x@W0 + label@W1 + P*va[j] + M*vc[j]
//                  + sum_d et0[n,d] * g[src[n,d], j] )
// ---------------------------------------------------------------------------
__global__ __launch_bounds__(128) void main_kernel(const float* __restrict__ x,
                                                   const float* __restrict__ label,
                                                   const float* __restrict__ w,
                                                   const float* __restrict__ e_type,
                                                   const int*   __restrict__ src,
                                                   const float* __restrict__ W0,
                                                   const float* __restrict__ W1,
                                                   float* __restrict__ out) {
    const int n   = blockIdx.x;
    const int tid = threadIdx.x;

    __shared__ int   srcs[DD];
    __shared__ float et[DD];
    __shared__ float sPM[2];

    if (tid < DD) {  // warp 0, full warp active
        int   sidx = src[n * DD + tid];
        float e0   = e_type[(n * DD + tid) * 2];
        srcs[tid] = sidx;
        et[tid]   = e0;
        float wv = w[n * DD + tid] * e0;
        float p = fmaxf(wv, 0.f);
        float m = fminf(wv, 0.f);
#pragma unroll
        for (int o = 16; o > 0; o >>= 1) {
            p += __shfl_down_sync(0xffffffffu, p, o);
            m += __shfl_down_sync(0xffffffffu, m, o);
        }
        if (tid == 0) { sPM[0] = p; sPM[1] = m; }
    }
    __syncthreads();

    const float P = sPM[0];
    const float M = sPM[1];
    const int j = tid;

    float acc = g_bias[j] + P * g_va[j] + M * g_vc[j];

    float x0 = x[n * 2 + 0];
    float x1 = x[n * 2 + 1];
    acc = fmaf(x0, W0[j], acc);
    acc = fmaf(x1, W0[HH + j], acc);

#pragma unroll
    for (int k = 0; k < KK; k++)
        acc = fmaf(label[n * KK + k], W1[k * HH + j], acc);

#pragma unroll 8
    for (int d = 0; d < DD; d++)
        acc = fmaf(et[d], g_buf[srcs[d] * HH + j], acc);

    out[n * HH + j] = fmaxf(acc, 0.f);
}

// ---------------------------------------------------------------------------
// kernel_launch
// metadata order: 0 feature, 1 x, 2 label, 3 w, 4 e_type, 5 src,
//                 6 W0, 7 b0, 8 W1, 9 b1, 10 W2, 11 b2, 12 Wt3, 13 Wt4
// ---------------------------------------------------------------------------
extern "C" void kernel_launch(void* const* d_in, const int* in_sizes, int n_in,
                              void* d_out, int out_size) {
    const float* feature = (const float*)d_in[0];
    const float* x       = (const float*)d_in[1];
    const float* label   = (const float*)d_in[2];
    const float* w       = (const float*)d_in[3];
    const float* e_type  = (const float*)d_in[4];
    const int*   src     = (const int*)  d_in[5];
    const float* W0      = (const float*)d_in[6];
    const float* b0      = (const float*)d_in[7];
    const float* W1      = (const float*)d_in[8];
    const float* b1      = (const float*)d_in[9];
    const float* W2      = (const float*)d_in[10];
    const float* b2      = (const float*)d_in[11];
    const float* Wt3     = (const float*)d_in[12];
    const float* Wt4     = (const float*)d_in[13];
    float* out = (float*)d_out;

    pre_kernel<<<1, 128>>>(Wt3, Wt4, b0, b1, b2);
    gemm_kernel<<<(NN + 127) / 128, 256>>>(feature, W2);
    main_kernel<<<NN, 128>>>(x, label, w, e_type, src, W0, W1, out);
}

// round 3
// speedup vs baseline: 1.2536x; 1.2536x over previous
#include <cuda_runtime.h>

#define NN 30000
#define DD 32
#define HH 128
#define KK 10

#define GEMM_BLOCKS ((NN + 127) / 128)   // 235

// Scratch (allocation-free rule: __device__ globals)
__device__ float g_buf[NN * HH];   // g = feature @ W2, 15.36 MB (L2-resident)
__device__ float g_va[HH];
__device__ float g_vc[HH];
__device__ float g_bias[HH];

// ---------------------------------------------------------------------------
// g = feature @ W2   ([NN,128] x [128,128] fp32)
// BM=128, BN=128, BK=32 (4 K-chunks). 256 threads, 8x8 micro-tile per thread.
// Last block (idx GEMM_BLOCKS) instead does the tiny precompute:
//   va[j] = sum_h max(Wt4[h],0)*Wt3[h,j], vc = min-part, bias[j] = b0+b1+b2.
// ---------------------------------------------------------------------------
__global__ __launch_bounds__(256) void gemm_kernel(const float* __restrict__ A,
                                                   const float* __restrict__ B,
                                                   const float* __restrict__ Wt3,
                                                   const float* __restrict__ Wt4,
                                                   const float* __restrict__ b0,
                                                   const float* __restrict__ b1,
                                                   const float* __restrict__ b2) {
    const int tid = threadIdx.x;

    if (blockIdx.x == GEMM_BLOCKS) {      // precompute block
        if (tid < HH) {
            int j = tid;
            float va = 0.f, vc = 0.f;
#pragma unroll 8
            for (int h = 0; h < HH; h++) {
                float t  = Wt4[h];
                float w3 = Wt3[h * HH + j];
                va += fmaxf(t, 0.f) * w3;
                vc += fminf(t, 0.f) * w3;
            }
            g_va[j]   = va;
            g_vc[j]   = vc;
            g_bias[j] = b0[j] + b1[j] + b2[j];
        }
        return;
    }

    __shared__ float As[128][32];   // [m][k-in-chunk]
    __shared__ float Bs[32][128];   // [k-in-chunk][n]
    const int row0 = blockIdx.x * 128;

    const int tx = tid & 15;   // output-column group (8 cols each)
    const int ty = tid >> 4;   // output-row group (8 rows each)

    float acc[8][8];
#pragma unroll
    for (int i = 0; i < 8; i++)
#pragma unroll
        for (int j = 0; j < 8; j++) acc[i][j] = 0.f;

    for (int kk = 0; kk < 4; kk++) {
        // Load A tile: 128 rows x 32 cols = 1024 float4, 4 per thread.
#pragma unroll
        for (int i = 0; i < 4; i++) {
            int f = tid + i * 256;
            int m = f >> 3;          // row within tile
            int q = f & 7;           // float4 index within 32-col chunk
            int row = row0 + m;
            float4 v = make_float4(0.f, 0.f, 0.f, 0.f);
            if (row < NN)
                v = reinterpret_cast<const float4*>(A)[row * 32 + kk * 8 + q];
            *reinterpret_cast<float4*>(&As[m][q * 4]) = v;
        }
        // Load B tile: 32 rows x 128 cols = 1024 float4, 4 per thread.
#pragma unroll
        for (int i = 0; i < 4; i++) {
            int f = tid + i * 256;
            int r = f >> 5;          // k-row within chunk
            int q = f & 31;          // float4 index within 128-col row
            float4 v = reinterpret_cast<const float4*>(B)[(kk * 32 + r) * 32 + q];
            *reinterpret_cast<float4*>(&Bs[r][q * 4]) = v;
        }
        __syncthreads();

#pragma unroll
        for (int k = 0; k < 32; k++) {
            float a[8], b[8];
#pragma unroll
            for (int i = 0; i < 8; i++) a[i] = As[ty * 8 + i][k];
            float4 bl = *reinterpret_cast<float4*>(&Bs[k][tx * 8]);
            float4 bh = *reinterpret_cast<float4*>(&Bs[k][tx * 8 + 4]);
            b[0] = bl.x; b[1] = bl.y; b[2] = bl.z; b[3] = bl.w;
            b[4] = bh.x; b[5] = bh.y; b[6] = bh.z; b[7] = bh.w;
#pragma unroll
            for (int i = 0; i < 8; i++)
#pragma unroll
                for (int j = 0; j < 8; j++) acc[i][j] = fmaf(a[i], b[j], acc[i][j]);
        }
        __syncthreads();
    }

#pragma unroll
    for (int i = 0; i < 8; i++) {
        int row = row0 + ty * 8 + i;
        if (row < NN) {
            float4* out = reinterpret_cast<float4*>(&g_buf[row * HH + tx * 8]);
            out[0] = make_float4(acc[i][0], acc[i][1], acc[i][2], acc[i][3]);
            out[1] = make_float4(acc[i][4], acc[i][5], acc[i][6], acc[i][7]);
        }
    }
}

// ---------------------------------------------------------------------------
// Fused gather + epilogue. 1 warp = 1 node; lane l owns columns 4l..4l+3.
// Edge metadata: lane d holds edge d in registers; broadcast via shfl.
// out[n,j] = relu( bias[j] + x@W0 + label@W1 + P*va[j] + M*vc[j]
//                  + sum_d et0[n,d] * g[src[n,d], j] )
// 256 threads/block = 8 nodes. 30000 % 8 == 0 -> no tail.
// ---------------------------------------------------------------------------
__global__ __launch_bounds__(256) void main_kernel(const float* __restrict__ x,
                                                   const float* __restrict__ label,
                                                   const float* __restrict__ w,
                                                   const float* __restrict__ e_type,
                                                   const int*   __restrict__ src,
                                                   const float* __restrict__ W0,
                                                   const float* __restrict__ W1,
                                                   float* __restrict__ out) {
    const int warp = threadIdx.x >> 5;
    const int lane = threadIdx.x & 31;
    const int n    = blockIdx.x * 8 + warp;

    // Each lane owns edge d = lane.
    const int   my_src = src[n * DD + lane];
    const float my_et  = e_type[(n * DD + lane) * 2];
    const float wv     = w[n * DD + lane] * my_et;

    // Butterfly-reduce P (relu+ part) and M (relu- part) to all lanes.
    float p = fmaxf(wv, 0.f);
    float m = fminf(wv, 0.f);
#pragma unroll
    for (int o = 16; o > 0; o >>= 1) {
        p += __shfl_xor_sync(0xffffffffu, p, o);
        m += __shfl_xor_sync(0xffffffffu, m, o);
    }

    const int c4 = lane * 4;   // first of 4 owned columns

    float4 bias = *reinterpret_cast<const float4*>(&g_bias[c4]);
    float4 va   = *reinterpret_cast<const float4*>(&g_va[c4]);
    float4 vc   = *reinterpret_cast<const float4*>(&g_vc[c4]);

    float4 acc;
    acc.x = fmaf(p, va.x, fmaf(m, vc.x, bias.x));
    acc.y = fmaf(p, va.y, fmaf(m, vc.y, bias.y));
    acc.z = fmaf(p, va.z, fmaf(m, vc.z, bias.z));
    acc.w = fmaf(p, va.w, fmaf(m, vc.w, bias.w));

    const float x0 = x[n * 2 + 0];
    const float x1 = x[n * 2 + 1];
    float4 w0a = *reinterpret_cast<const float4*>(&W0[c4]);
    float4 w0b = *reinterpret_cast<const float4*>(&W0[HH + c4]);
    acc.x = fmaf(x0, w0a.x, fmaf(x1, w0b.x, acc.x));
    acc.y = fmaf(x0, w0a.y, fmaf(x1, w0b.y, acc.y));
    acc.z = fmaf(x0, w0a.z, fmaf(x1, w0b.z, acc.z));
    acc.w = fmaf(x0, w0a.w, fmaf(x1, w0b.w, acc.w));

#pragma unroll
    for (int k = 0; k < KK; k++) {
        float lk = label[n * KK + k];           // warp-uniform -> broadcast
        float4 w1 = *reinterpret_cast<const float4*>(&W1[k * HH + c4]);
        acc.x = fmaf(lk, w1.x, acc.x);
        acc.y = fmaf(lk, w1.y, acc.y);
        acc.z = fmaf(lk, w1.z, acc.z);
        acc.w = fmaf(lk, w1.w, acc.w);
    }

    // Gather-reduce over the 32 edges. 1 LDG.128 per lane per edge.
#pragma unroll
    for (int d = 0; d < DD; d++) {
        int   sd = __shfl_sync(0xffffffffu, my_src, d);
        float ed = __shfl_sync(0xffffffffu, my_et, d);
        float4 gv = *reinterpret_cast<const float4*>(&g_buf[sd * HH + c4]);
        acc.x = fmaf(ed, gv.x, acc.x);
        acc.y = fmaf(ed, gv.y, acc.y);
        acc.z = fmaf(ed, gv.z, acc.z);
        acc.w = fmaf(ed, gv.w, acc.w);
    }

    float4 res;
    res.x = fmaxf(acc.x, 0.f);
    res.y = fmaxf(acc.y, 0.f);
    res.z = fmaxf(acc.z, 0.f);
    res.w = fmaxf(acc.w, 0.f);
    *reinterpret_cast<float4*>(&out[n * HH + c4]) = res;
}

// ---------------------------------------------------------------------------
// kernel_launch
// metadata order: 0 feature, 1 x, 2 label, 3 w, 4 e_type, 5 src,
//                 6 W0, 7 b0, 8 W1, 9 b1, 10 W2, 11 b2, 12 Wt3, 13 Wt4
// ---------------------------------------------------------------------------
extern "C" void kernel_launch(void* const* d_in, const int* in_sizes, int n_in,
                              void* d_out, int out_size) {
    const float* feature = (const float*)d_in[0];
    const float* x       = (const float*)d_in[1];
    const float* label   = (const float*)d_in[2];
    const float* w       = (const float*)d_in[3];
    const float* e_type  = (const float*)d_in[4];
    const int*   src     = (const int*)  d_in[5];
    const float* W0      = (const float*)d_in[6];
    const float* b0      = (const float*)d_in[7];
    const float* W1      = (const float*)d_in[8];
    const float* b1      = (const float*)d_in[9];
    const float* W2      = (const float*)d_in[10];
    const float* b2      = (const float*)d_in[11];
    const float* Wt3     = (const float*)d_in[12];
    const float* Wt4     = (const float*)d_in[13];
    float* out = (float*)d_out;

    gemm_kernel<<<GEMM_BLOCKS + 1, 256>>>(feature, W2, Wt3, Wt4, b0, b1, b2);
    main_kernel<<<NN / 8, 256>>>(x, label, w, e_type, src, W0, W1, out);
}

// round 4
// speedup vs baseline: 1.4771x; 1.1784x over previous
#include <cuda_runtime.h>
#include <cuda_fp16.h>

#define NN 30000
#define DD 32
#define HH 128
#define KK 10

#define GEMM_BLOCKS ((NN + 127) / 128)   // 235

// Scratch (allocation-free rule: __device__ globals)
__device__ __half g_buf[NN * HH];   // g = feature @ W2 in fp16, 7.68 MB (L2-resident)
__device__ float  g_va[HH];
__device__ float  g_vc[HH];
__device__ float  g_bias[HH];

// ---------------------------------------------------------------------------
// g = feature @ W2   ([NN,128] x [128,128], fp32 math, fp16 store)
// BM=128, BN=128, BK=32 (4 K-chunks). 256 threads, 8x8 micro-tile per thread.
// Last block (idx GEMM_BLOCKS) instead does the tiny precompute:
//   va[j] = sum_h max(Wt4[h],0)*Wt3[h,j], vc = min-part, bias[j] = b0+b1+b2.
// ---------------------------------------------------------------------------
__global__ __launch_bounds__(256) void gemm_kernel(const float* __restrict__ A,
                                                   const float* __restrict__ B,
                                                   const float* __restrict__ Wt3,
                                                   const float* __restrict__ Wt4,
                                                   const float* __restrict__ b0,
                                                   const float* __restrict__ b1,
                                                   const float* __restrict__ b2) {
    const int tid = threadIdx.x;

    if (blockIdx.x == GEMM_BLOCKS) {      // precompute block
        if (tid < HH) {
            int j = tid;
            float va = 0.f, vc = 0.f;
#pragma unroll 8
            for (int h = 0; h < HH; h++) {
                float t  = Wt4[h];
                float w3 = Wt3[h * HH + j];
                va += fmaxf(t, 0.f) * w3;
                vc += fminf(t, 0.f) * w3;
            }
            g_va[j]   = va;
            g_vc[j]   = vc;
            g_bias[j] = b0[j] + b1[j] + b2[j];
        }
        return;
    }

    __shared__ float As[128][32];   // [m][k-in-chunk]
    __shared__ float Bs[32][128];   // [k-in-chunk][n]
    const int row0 = blockIdx.x * 128;

    const int tx = tid & 15;   // output-column group (8 cols each)
    const int ty = tid >> 4;   // output-row group (8 rows each)

    float acc[8][8];
#pragma unroll
    for (int i = 0; i < 8; i++)
#pragma unroll
        for (int j = 0; j < 8; j++) acc[i][j] = 0.f;

    for (int kk = 0; kk < 4; kk++) {
        // Load A tile: 128 rows x 32 cols = 1024 float4, 4 per thread.
#pragma unroll
        for (int i = 0; i < 4; i++) {
            int f = tid + i * 256;
            int m = f >> 3;          // row within tile
            int q = f & 7;           // float4 index within 32-col chunk
            int row = row0 + m;
            float4 v = make_float4(0.f, 0.f, 0.f, 0.f);
            if (row < NN)
                v = reinterpret_cast<const float4*>(A)[row * 32 + kk * 8 + q];
            *reinterpret_cast<float4*>(&As[m][q * 4]) = v;
        }
        // Load B tile: 32 rows x 128 cols = 1024 float4, 4 per thread.
#pragma unroll
        for (int i = 0; i < 4; i++) {
            int f = tid + i * 256;
            int r = f >> 5;          // k-row within chunk
            int q = f & 31;          // float4 index within 128-col row
            float4 v = reinterpret_cast<const float4*>(B)[(kk * 32 + r) * 32 + q];
            *reinterpret_cast<float4*>(&Bs[r][q * 4]) = v;
        }
        __syncthreads();

#pragma unroll
        for (int k = 0; k < 32; k++) {
            float a[8], b[8];
#pragma unroll
            for (int i = 0; i < 8; i++) a[i] = As[ty * 8 + i][k];
            float4 bl = *reinterpret_cast<float4*>(&Bs[k][tx * 8]);
            float4 bh = *reinterpret_cast<float4*>(&Bs[k][tx * 8 + 4]);
            b[0] = bl.x; b[1] = bl.y; b[2] = bl.z; b[3] = bl.w;
            b[4] = bh.x; b[5] = bh.y; b[6] = bh.z; b[7] = bh.w;
#pragma unroll
            for (int i = 0; i < 8; i++)
#pragma unroll
                for (int j = 0; j < 8; j++) acc[i][j] = fmaf(a[i], b[j], acc[i][j]);
        }
        __syncthreads();
    }

    // Store as fp16: 8 halves per row-slice = 16 bytes = one uint4.
#pragma unroll
    for (int i = 0; i < 8; i++) {
        int row = row0 + ty * 8 + i;
        if (row < NN) {
            __half2 h[4];
            h[0] = __floats2half2_rn(acc[i][0], acc[i][1]);
            h[1] = __floats2half2_rn(acc[i][2], acc[i][3]);
            h[2] = __floats2half2_rn(acc[i][4], acc[i][5]);
            h[3] = __floats2half2_rn(acc[i][6], acc[i][7]);
            *reinterpret_cast<uint4*>(&g_buf[row * HH + tx * 8]) =
                *reinterpret_cast<uint4*>(h);
        }
    }
}

// ---------------------------------------------------------------------------
// Fused gather + epilogue. 1 warp = 1 node; lane l owns columns 4l..4l+3.
// Edge metadata: lane d holds edge d in registers; broadcast via shfl.
// Gather reads fp16 g rows (LDG.64 per lane), fp32 accumulate.
// 256 threads/block = 8 nodes. 30000 % 8 == 0 -> no tail.
// ---------------------------------------------------------------------------
__global__ __launch_bounds__(256) void main_kernel(const float* __restrict__ x,
                                                   const float* __restrict__ label,
                                                   const float* __restrict__ w,
                                                   const float* __restrict__ e_type,
                                                   const int*   __restrict__ src,
                                                   const float* __restrict__ W0,
                                                   const float* __restrict__ W1,
                                                   float* __restrict__ out) {
    const int warp = threadIdx.x >> 5;
    const int lane = threadIdx.x & 31;
    const int n    = blockIdx.x * 8 + warp;

    // Each lane owns edge d = lane.
    const int   my_src = src[n * DD + lane];
    const float my_et  = e_type[(n * DD + lane) * 2];
    const float wv     = w[n * DD + lane] * my_et;

    // Butterfly-reduce P (relu+ part) and M (relu- part) to all lanes.
    float p = fmaxf(wv, 0.f);
    float m = fminf(wv, 0.f);
#pragma unroll
    for (int o = 16; o > 0; o >>= 1) {
        p += __shfl_xor_sync(0xffffffffu, p, o);
        m += __shfl_xor_sync(0xffffffffu, m, o);
    }

    const int c4 = lane * 4;   // first of 4 owned columns

    float4 bias = *reinterpret_cast<const float4*>(&g_bias[c4]);
    float4 va   = *reinterpret_cast<const float4*>(&g_va[c4]);
    float4 vc   = *reinterpret_cast<const float4*>(&g_vc[c4]);

    float4 acc;
    acc.x = fmaf(p, va.x, fmaf(m, vc.x, bias.x));
    acc.y = fmaf(p, va.y, fmaf(m, vc.y, bias.y));
    acc.z = fmaf(p, va.z, fmaf(m, vc.z, bias.z));
    acc.w = fmaf(p, va.w, fmaf(m, vc.w, bias.w));

    const float x0 = x[n * 2 + 0];
    const float x1 = x[n * 2 + 1];
    float4 w0a = *reinterpret_cast<const float4*>(&W0[c4]);
    float4 w0b = *reinterpret_cast<const float4*>(&W0[HH + c4]);
    acc.x = fmaf(x0, w0a.x, fmaf(x1, w0b.x, acc.x));
    acc.y = fmaf(x0, w0a.y, fmaf(x1, w0b.y, acc.y));
    acc.z = fmaf(x0, w0a.z, fmaf(x1, w0b.z, acc.z));
    acc.w = fmaf(x0, w0a.w, fmaf(x1, w0b.w, acc.w));

#pragma unroll
    for (int k = 0; k < KK; k++) {
        float lk = label[n * KK + k];           // warp-uniform -> broadcast
        float4 w1 = *reinterpret_cast<const float4*>(&W1[k * HH + c4]);
        acc.x = fmaf(lk, w1.x, acc.x);
        acc.y = fmaf(lk, w1.y, acc.y);
        acc.z = fmaf(lk, w1.z, acc.z);
        acc.w = fmaf(lk, w1.w, acc.w);
    }

    // Gather-reduce over the 32 edges. 1 LDG.64 (4 fp16 cols) per lane per edge.
#pragma unroll
    for (int d = 0; d < DD; d++) {
        int   sd = __shfl_sync(0xffffffffu, my_src, d);
        float ed = __shfl_sync(0xffffffffu, my_et, d);
        uint2 raw = *reinterpret_cast<const uint2*>(&g_buf[sd * HH + c4]);
        float2 f01 = __half22float2(*reinterpret_cast<__half2*>(&raw.x));
        float2 f23 = __half22float2(*reinterpret_cast<__half2*>(&raw.y));
        acc.x = fmaf(ed, f01.x, acc.x);
        acc.y = fmaf(ed, f01.y, acc.y);
        acc.z = fmaf(ed, f23.x, acc.z);
        acc.w = fmaf(ed, f23.y, acc.w);
    }

    float4 res;
    res.x = fmaxf(acc.x, 0.f);
    res.y = fmaxf(acc.y, 0.f);
    res.z = fmaxf(acc.z, 0.f);
    res.w = fmaxf(acc.w, 0.f);
    *reinterpret_cast<float4*>(&out[n * HH + c4]) = res;
}

// ---------------------------------------------------------------------------
// kernel_launch
// metadata order: 0 feature, 1 x, 2 label, 3 w, 4 e_type, 5 src,
//                 6 W0, 7 b0, 8 W1, 9 b1, 10 W2, 11 b2, 12 Wt3, 13 Wt4
// ---------------------------------------------------------------------------
extern "C" void kernel_launch(void* const* d_in, const int* in_sizes, int n_in,
                              void* d_out, int out_size) {
    const float* feature = (const float*)d_in[0];
    const float* x       = (const float*)d_in[1];
    const float* label   = (const float*)d_in[2];
    const float* w       = (const float*)d_in[3];
    const float* e_type  = (const float*)d_in[4];
    const int*   src     = (const int*)  d_in[5];
    const float* W0      = (const float*)d_in[6];
    const float* b0      = (const float*)d_in[7];
    const float* W1      = (const float*)d_in[8];
    const float* b1      = (const float*)d_in[9];
    const float* W2      = (const float*)d_in[10];
    const float* b2      = (const float*)d_in[11];
    const float* Wt3     = (const float*)d_in[12];
    const float* Wt4     = (const float*)d_in[13];
    float* out = (float*)d_out;

    gemm_kernel<<<GEMM_BLOCKS + 1, 256>>>(feature, W2, Wt3, Wt4, b0, b1, b2);
    main_kernel<<<NN / 8, 256>>>(x, label, w, e_type, src, W0, W1, out);
}

// round 5
// speedup vs baseline: 1.6659x; 1.1278x over previous
#include <cuda_runtime.h>
#include <cuda_fp16.h>
#include <mma.h>

using namespace nvcuda;

#define NN 30000
#define DD 32
#define HH 128
#define KK 10

#define GEMM_BLOCKS ((NN + 127) / 128)   // 235

// Scratch (allocation-free rule: __device__ globals)
__device__ __half g_buf[NN * HH];   // g = feature @ W2 in fp16, 7.68 MB
__device__ float  g_va[HH];
__device__ float  g_vc[HH];
__device__ float  g_bias[HH];

// ---------------------------------------------------------------------------
// g = feature @ W2 via wmma (fp16 inputs, fp32 accumulate, fp16 store).
// BM=128, BN=128, BK=64 (2 K-chunks). 256 threads = 8 warps.
// Warp w: warpM = w%4 (32 rows), warpN = w/4 (64 cols) -> 2x4 acc frags 16x16.
// Smem: As 128x64 fp16 (16KB) + Bs 64x128 fp16 (16KB) = 32KB; reused as
// fp32 staging (8 warps x 16x64) in the epilogue.
// Last block (idx GEMM_BLOCKS) does the tiny precompute instead.
// ---------------------------------------------------------------------------
__global__ __launch_bounds__(256) void gemm_kernel(const float* __restrict__ A,
                                                   const float* __restrict__ B,
                                                   const float* __restrict__ Wt3,
                                                   const float* __restrict__ Wt4,
                                                   const float* __restrict__ b0,
                                                   const float* __restrict__ b1,
                                                   const float* __restrict__ b2) {
    const int tid = threadIdx.x;

    if (blockIdx.x == GEMM_BLOCKS) {      // precompute block
        if (tid < HH) {
            int j = tid;
            float va = 0.f, vc = 0.f;
#pragma unroll 8
            for (int h = 0; h < HH; h++) {
                float t  = Wt4[h];
                float w3 = Wt3[h * HH + j];
                va += fmaxf(t, 0.f) * w3;
                vc += fminf(t, 0.f) * w3;
            }
            g_va[j]   = va;
            g_vc[j]   = vc;
            g_bias[j] = b0[j] + b1[j] + b2[j];
        }
        return;
    }

    __shared__ __half As[128 * 64];   // [m][k], ld=64
    __shared__ __half Bs[64 * 128];   // [k][n], ld=128

    const int row0  = blockIdx.x * 128;
    const int wid   = tid >> 5;
    const int lane  = tid & 31;
    const int warpM = wid & 3;        // 0..3 -> 32-row slab
    const int warpN = wid >> 2;       // 0..1 -> 64-col slab

    wmma::fragment<wmma::accumulator, 16, 16, 16, float> acc[2][4];
#pragma unroll
    for (int mg = 0; mg < 2; mg++)
#pragma unroll
        for (int nf = 0; nf < 4; nf++)
            wmma::fill_fragment(acc[mg][nf], 0.f);

    for (int kk = 0; kk < 2; kk++) {
        // Load A chunk: 128 rows x 64 cols fp32 -> fp16 smem. 2048 float4, 8/thread.
#pragma unroll
        for (int i = 0; i < 8; i++) {
            int f = tid + i * 256;
            int m = f >> 4;            // row in tile
            int q = f & 15;            // float4 within 64-col chunk
            int row = row0 + m;
            float4 v = make_float4(0.f, 0.f, 0.f, 0.f);
            if (row < NN)
                v = *reinterpret_cast<const float4*>(&A[row * HH + kk * 64 + q * 4]);
            __half h[4] = {__float2half_rn(v.x), __float2half_rn(v.y),
                           __float2half_rn(v.z), __float2half_rn(v.w)};
            *reinterpret_cast<uint2*>(&As[m * 64 + q * 4]) = *reinterpret_cast<uint2*>(h);
        }
        // Load B chunk: 64 rows x 128 cols fp32 -> fp16 smem. 2048 float4, 8/thread.
#pragma unroll
        for (int i = 0; i < 8; i++) {
            int f = tid + i * 256;
            int r = f >> 5;            // k-row within chunk
            int q = f & 31;            // float4 within 128-col row
            float4 v = *reinterpret_cast<const float4*>(&B[(kk * 64 + r) * HH + q * 4]);
            __half h[4] = {__float2half_rn(v.x), __float2half_rn(v.y),
                           __float2half_rn(v.z), __float2half_rn(v.w)};
            *reinterpret_cast<uint2*>(&Bs[r * 128 + q * 4]) = *reinterpret_cast<uint2*>(h);
        }
        __syncthreads();

#pragma unroll
        for (int k = 0; k < 4; k++) {   // 4 k16 steps per chunk
            wmma::fragment<wmma::matrix_a, 16, 16, 16, __half, wmma::row_major> af[2];
            wmma::fragment<wmma::matrix_b, 16, 16, 16, __half, wmma::row_major> bf[4];
#pragma unroll
            for (int mg = 0; mg < 2; mg++)
                wmma::load_matrix_sync(af[mg],
                    &As[(warpM * 32 + mg * 16) * 64 + k * 16], 64);
#pragma unroll
            for (int nf = 0; nf < 4; nf++)
                wmma::load_matrix_sync(bf[nf],
                    &Bs[(k * 16) * 128 + warpN * 64 + nf * 16], 128);
#pragma unroll
            for (int mg = 0; mg < 2; mg++)
#pragma unroll
                for (int nf = 0; nf < 4; nf++)
                    wmma::mma_sync(acc[mg][nf], af[mg], bf[nf], acc[mg][nf]);
        }
        __syncthreads();
    }

    // Epilogue: stage fp32 per warp (16x64 = 4KB each), convert, store fp16.
    float* stage = reinterpret_cast<float*>(As);   // 32KB total, per-warp slice
    float* ws = stage + wid * 1024;
#pragma unroll
    for (int mg = 0; mg < 2; mg++) {
#pragma unroll
        for (int nf = 0; nf < 4; nf++)
            wmma::store_matrix_sync(ws + nf * 16, acc[mg][nf], 64, wmma::mem_row_major);
        __syncwarp();

        int r     = lane >> 1;               // 16 rows, 2 lanes per row
        int cbase = (lane & 1) * 32;         // 32 cols per lane
        int row   = row0 + warpM * 32 + mg * 16 + r;
        if (row < NN) {
            const float* src_row = ws + r * 64 + cbase;
            __half h[32];
#pragma unroll
            for (int j = 0; j < 32; j++) h[j] = __float2half_rn(src_row[j]);
            uint4* dst = reinterpret_cast<uint4*>(&g_buf[row * HH + warpN * 64 + cbase]);
            const uint4* hs = reinterpret_cast<const uint4*>(h);
            dst[0] = hs[0]; dst[1] = hs[1]; dst[2] = hs[2]; dst[3] = hs[3];
        }
        __syncwarp();
    }
}

// ---------------------------------------------------------------------------
// Fused gather + epilogue. 1 warp = 1 node; lane l owns columns 4l..4l+3.
// Edge metadata staged in smem; per-edge uniform LDS.64 broadcast (no shfl).
// 256 threads/block = 8 nodes. 30000 % 8 == 0 -> no tail.
// ---------------------------------------------------------------------------
__global__ __launch_bounds__(256) void main_kernel(const float* __restrict__ x,
                                                   const float* __restrict__ label,
                                                   const float* __restrict__ w,
                                                   const float* __restrict__ e_type,
                                                   const int*   __restrict__ src,
                                                   const float* __restrict__ W0,
                                                   const float* __restrict__ W1,
                                                   float* __restrict__ out) {
    const int warp = threadIdx.x >> 5;
    const int lane = threadIdx.x & 31;
    const int n    = blockIdx.x * 8 + warp;

    __shared__ int2 meta[8][DD];   // {src*HH, bits(et)} per edge, 2KB

    // Lane d stages edge d; compute wv for the P/M reduction.
    const int   my_src = src[n * DD + lane];
    const float my_et  = e_type[(n * DD + lane) * 2];
    const float wv     = w[n * DD + lane] * my_et;
    meta[warp][lane] = make_int2(my_src * HH, __float_as_int(my_et));
    __syncwarp();

    // Butterfly-reduce P (relu+ part) and M (relu- part) to all lanes.
    float p = fmaxf(wv, 0.f);
    float m = fminf(wv, 0.f);
#pragma unroll
    for (int o = 16; o > 0; o >>= 1) {
        p += __shfl_xor_sync(0xffffffffu, p, o);
        m += __shfl_xor_sync(0xffffffffu, m, o);
    }

    const int c4 = lane * 4;   // first of 4 owned columns

    float4 bias = *reinterpret_cast<const float4*>(&g_bias[c4]);
    float4 va   = *reinterpret_cast<const float4*>(&g_va[c4]);
    float4 vc   = *reinterpret_cast<const float4*>(&g_vc[c4]);

    float4 acc;
    acc.x = fmaf(p, va.x, fmaf(m, vc.x, bias.x));
    acc.y = fmaf(p, va.y, fmaf(m, vc.y, bias.y));
    acc.z = fmaf(p, va.z, fmaf(m, vc.z, bias.z));
    acc.w = fmaf(p, va.w, fmaf(m, vc.w, bias.w));

    const float x0 = x[n * 2 + 0];
    const float x1 = x[n * 2 + 1];
    float4 w0a = *reinterpret_cast<const float4*>(&W0[c4]);
    float4 w0b = *reinterpret_cast<const float4*>(&W0[HH + c4]);
    acc.x = fmaf(x0, w0a.x, fmaf(x1, w0b.x, acc.x));
    acc.y = fmaf(x0, w0a.y, fmaf(x1, w0b.y, acc.y));
    acc.z = fmaf(x0, w0a.z, fmaf(x1, w0b.z, acc.z));
    acc.w = fmaf(x0, w0a.w, fmaf(x1, w0b.w, acc.w));

#pragma unroll
    for (int k = 0; k < KK; k++) {
        float lk = label[n * KK + k];           // warp-uniform -> broadcast
        float4 w1 = *reinterpret_cast<const float4*>(&W1[k * HH + c4]);
        acc.x = fmaf(lk, w1.x, acc.x);
        acc.y = fmaf(lk, w1.y, acc.y);
        acc.z = fmaf(lk, w1.z, acc.z);
        acc.w = fmaf(lk, w1.w, acc.w);
    }

    // Gather-reduce: per edge 1 uniform LDS.64 + 1 LDG.64 (4 fp16 cols/lane).
#pragma unroll 8
    for (int d = 0; d < DD; d++) {
        int2  e  = meta[warp][d];               // uniform address -> broadcast
        float ed = __int_as_float(e.y);
        uint2 raw = *reinterpret_cast<const uint2*>(&g_buf[e.x + c4]);
        float2 f01 = __half22float2(*reinterpret_cast<__half2*>(&raw.x));
        float2 f23 = __half22float2(*reinterpret_cast<__half2*>(&raw.y));
        acc.x = fmaf(ed, f01.x, acc.x);
        acc.y = fmaf(ed, f01.y, acc.y);
        acc.z = fmaf(ed, f23.x, acc.z);
        acc.w = fmaf(ed, f23.y, acc.w);
    }

    float4 res;
    res.x = fmaxf(acc.x, 0.f);
    res.y = fmaxf(acc.y, 0.f);
    res.z = fmaxf(acc.z, 0.f);
    res.w = fmaxf(acc.w, 0.f);
    *reinterpret_cast<float4*>(&out[n * HH + c4]) = res;
}

// ---------------------------------------------------------------------------
// kernel_launch
// metadata order: 0 feature, 1 x, 2 label, 3 w, 4 e_type, 5 src,
//                 6 W0, 7 b0, 8 W1, 9 b1, 10 W2, 11 b2, 12 Wt3, 13 Wt4
// ---------------------------------------------------------------------------
extern "C" void kernel_launch(void* const* d_in, const int* in_sizes, int n_in,
                              void* d_out, int out_size) {
    const float* feature = (const float*)d_in[0];
    const float* x       = (const float*)d_in[1];
    const float* label   = (const float*)d_in[2];
    const float* w       = (const float*)d_in[3];
    const float* e_type  = (const float*)d_in[4];
    const int*   src     = (const int*)  d_in[5];
    const float* W0      = (const float*)d_in[6];
    const float* b0      = (const float*)d_in[7];
    const float* W1      = (const float*)d_in[8];
    const float* b1      = (const float*)d_in[9];
    const float* W2      = (const float*)d_in[10];
    const float* b2      = (const float*)d_in[11];
    const float* Wt3     = (const float*)d_in[12];
    const float* Wt4     = (const float*)d_in[13];
    float* out = (float*)d_out;

    gemm_kernel<<<GEMM_BLOCKS + 1, 256>>>(feature, W2, Wt3, Wt4, b0, b1, b2);
    main_kernel<<<NN / 8, 256>>>(x, label, w, e_type, src, W0, W1, out);
}